// round 9
// baseline (speedup 1.0000x reference)
#include <cuda_runtime.h>
#include <math.h>
#include <stdint.h>

#define H 1024
#define V 50257
#define L 128
#define NB 592                 // grid: 148 SMs x 4 resident (one wave, co-resident)
#define TB 16384u              // tile bytes: 4 rows x 1024 floats

// ---- persistent scratch (zero-initialized by loader) ----
__device__ __align__(16) float g_attn_scratch[L];
__device__ __align__(16) float g_attn_applied[H];
__device__ __align__(16) float g_x[H];
__device__ __align__(16) float g_h[H];
__device__ __align__(16) float g_gates[4 * H];     // must be zero at kernel entry
__device__ __align__(16) float g_bmax[NB];
__device__ __align__(16) float g_bsum[NB];
__device__ float    g_logZ;
__device__ unsigned g_ctr_attn, g_ctr_aa, g_ctr_comb, g_ctr_gate, g_ctr_out, g_done;
__device__ unsigned g_flag_sm, g_flag_aa, g_flag_x, g_flag_h, g_flag_z;

__device__ __forceinline__ float warp_sum(float v) {
    #pragma unroll
    for (int o = 16; o; o >>= 1) v += __shfl_down_sync(0xffffffffu, v, o);
    return v;
}
__device__ __forceinline__ float warp_max(float v) {
    #pragma unroll
    for (int o = 16; o; o >>= 1) v = fmaxf(v, __shfl_down_sync(0xffffffffu, v, o));
    return v;
}
__device__ __forceinline__ float dot4(float4 a, float4 b) {
    return a.x * b.x + a.y * b.y + a.z * b.z + a.w * b.w;
}
__device__ __forceinline__ uint64_t mkpolicy() {
    uint64_t p;
    asm("createpolicy.fractional.L2::evict_first.b64 %0, 1.0;" : "=l"(p));
    return p;
}
__device__ __forceinline__ void bulk_cp(void* dst_smem, const void* src,
                                        unsigned bytes, unsigned mbar, uint64_t pol) {
    unsigned d = (unsigned)__cvta_generic_to_shared(dst_smem);
    asm volatile(
        "cp.async.bulk.shared::cluster.global.mbarrier::complete_tx::bytes.L2::cache_hint"
        " [%0], [%1], %2, [%3], %4;"
        :: "r"(d), "l"(src), "r"(bytes), "r"(mbar), "l"(pol) : "memory");
}
__device__ __forceinline__ void mbar_init(unsigned mbar, unsigned cnt) {
    asm volatile("mbarrier.init.shared.b64 [%0], %1;" :: "r"(mbar), "r"(cnt) : "memory");
}
__device__ __forceinline__ void mbar_expect(unsigned mbar, unsigned bytes) {
    asm volatile("mbarrier.arrive.expect_tx.shared.b64 _, [%0], %1;"
                 :: "r"(mbar), "r"(bytes) : "memory");
}
__device__ __forceinline__ void mbar_wait(unsigned mbar, unsigned parity) {
    asm volatile(
        "{\n\t.reg .pred P;\n\t"
        "W_%=:\n\t"
        "mbarrier.try_wait.parity.acquire.cta.shared::cta.b64 P, [%0], %1, 0x989680;\n\t"
        "@P bra.uni D_%=;\n\t"
        "bra.uni W_%=;\n\t"
        "D_%=:\n\t}"
        :: "r"(mbar), "r"(parity) : "memory");
}
__device__ __forceinline__ unsigned smem_u32(const void* p) {
    return (unsigned)__cvta_generic_to_shared(p);
}
__device__ __forceinline__ void spin_flag(unsigned* f) {
    while (*(volatile unsigned*)f == 0u) __nanosleep(64);
}

// LSTM pointwise performed by the block that counts the 2048th gate tile.
__device__ __forceinline__ void lstm_all(const float* __restrict__ c0,
                                         const float* __restrict__ b_ih,
                                         const float* __restrict__ b_hh,
                                         float* __restrict__ h_out,
                                         float* __restrict__ c_out, int tid) {
    __threadfence();
    for (int u = tid; u < H; u += 128) {
        float gi = g_gates[u]         + b_ih[u]         + b_hh[u];
        float gf = g_gates[H + u]     + b_ih[H + u]     + b_hh[H + u];
        float gg = g_gates[2 * H + u] + b_ih[2 * H + u] + b_hh[2 * H + u];
        float go = g_gates[3 * H + u] + b_ih[3 * H + u] + b_hh[3 * H + u];
        float ig = 1.f / (1.f + expf(-gi));
        float fg = 1.f / (1.f + expf(-gf));
        float gt = tanhf(gg);
        float og = 1.f / (1.f + expf(-go));
        float cn = fg * c0[u] + ig * gt;
        float hn = og * tanhf(cn);
        c_out[u] = cn; h_out[u] = hn; g_h[u] = hn;
        g_gates[u] = 0.f; g_gates[H + u] = 0.f;
        g_gates[2 * H + u] = 0.f; g_gates[3 * H + u] = 0.f;   // reset for next replay
    }
    __threadfence();
    __syncthreads();
    if (tid == 0) { g_ctr_gate = 0u; __threadfence(); atomicExch(&g_flag_h, 1u); }
    __syncthreads();
}

__global__ void __launch_bounds__(128, 4) k_fused(
    const int* __restrict__ tokens, const float* __restrict__ h0,
    const float* __restrict__ c0,   const float* __restrict__ enc,
    const float* __restrict__ emb,  const float* __restrict__ attn_W,
    const float* __restrict__ attn_b, const float* __restrict__ comb_W,
    const float* __restrict__ comb_b, const float* __restrict__ W_ih,
    const float* __restrict__ W_hh, const float* __restrict__ b_ih,
    const float* __restrict__ b_hh, const float* __restrict__ out_W,
    const float* __restrict__ out_b,
    float* __restrict__ out, float* __restrict__ h_out,
    float* __restrict__ c_out, float* __restrict__ aw_out)
{
    __shared__ __align__(128) float4 buf[2][1024];   // 32KB double buffer
    __shared__ float4   s_vec[256];                  // h0 -> g_x -> g_h
    __shared__ uint64_t mbar[2];
    __shared__ float    s_red[8];
    __shared__ float    s_soft[128];
    __shared__ unsigned s_bcast;

    const int tid = threadIdx.x, warp = tid >> 5, lane = tid & 31;
    const int b = blockIdx.x;
    uint64_t pol = mkpolicy();
    unsigned mb0 = smem_u32(&mbar[0]), mb1 = smem_u32(&mbar[1]);
    int p0 = 0, p1 = 0;

    if (tid == 0) { mbar_init(mb0, 1); mbar_init(mb1, 1); }
    s_vec[tid]       = ((const float4*)h0)[tid];
    s_vec[tid + 128] = ((const float4*)h0)[tid + 128];
    __syncthreads();

    // ---- issue W_hh tile copies immediately (no dependency) ----
    if (tid == 0) {
        mbar_expect(mb0, TB); bulk_cp(buf[0], W_hh + (size_t)b * 4 * H, TB, mb0, pol);
        if (b < 432) { mbar_expect(mb1, TB); bulk_cp(buf[1], W_hh + (size_t)(592 + b) * 4 * H, TB, mb1, pol); }
    }

    const float4* erow4 = (const float4*)(emb + (size_t)tokens[0] * H);

    // ---- attn logits (blocks 0..127) + softmax in last-arriving block ----
    if (b < L) {
        const float4* w = (const float4*)(attn_W + (size_t)b * 2 * H);
        float acc = 0.f;
        #pragma unroll
        for (int k = 0; k < 4; k++) {
            int i = tid + 128 * k;
            float4 xv = (i < 256) ? erow4[i] : s_vec[i - 256];
            acc += dot4(w[i], xv);
        }
        acc = warp_sum(acc);
        if (lane == 0) s_red[warp] = acc;
        __syncthreads();
        if (tid == 0) {
            g_attn_scratch[b] = s_red[0] + s_red[1] + s_red[2] + s_red[3] + attn_b[b];
            __threadfence();
            s_bcast = (atomicAdd(&g_ctr_attn, 1u) == L - 1);
        }
        __syncthreads();
        if (s_bcast) {
            __threadfence();
            float v = g_attn_scratch[tid];
            s_soft[tid] = v; __syncthreads();
            for (int st = 64; st; st >>= 1) { if (tid < st) s_soft[tid] = fmaxf(s_soft[tid], s_soft[tid + st]); __syncthreads(); }
            float M = s_soft[0]; __syncthreads();
            float e = expf(v - M);
            s_soft[tid] = e; __syncthreads();
            for (int st = 64; st; st >>= 1) { if (tid < st) s_soft[tid] += s_soft[tid + st]; __syncthreads(); }
            float wgt = e / s_soft[0];
            aw_out[tid] = wgt;
            g_attn_scratch[tid] = wgt;
            __threadfence(); __syncthreads();
            if (tid == 0) { g_ctr_attn = 0u; __threadfence(); atomicExch(&g_flag_sm, 1u); }
        }
        __syncthreads();
    }

    // ---- consume W_hh tile A (dot vs h0 in s_vec) ----
    mbar_wait(mb0, p0 & 1); p0++;
    {
        float a = 0.f;
        #pragma unroll
        for (int k = 0; k < 8; k++) a += dot4(buf[0][warp * 256 + lane + 32 * k], s_vec[lane + 32 * k]);
        a = warp_sum(a);
        if (lane == 0) atomicAdd(&g_gates[4 * b + warp], a);
    }
    __threadfence(); __syncthreads();
    if (tid == 0) s_bcast = (atomicAdd(&g_ctr_gate, 1u) == 2047u);
    __syncthreads();
    if (s_bcast) lstm_all(c0, b_ih, b_hh, h_out, c_out, tid);

    // issue comb tile copy into stage0 (copy needs nothing; dot waits on flag_aa)
    if (b < 512 && tid == 0) { mbar_expect(mb0, TB); bulk_cp(buf[0], comb_W + (size_t)b * 4 * H, TB, mb0, pol); }

    // ---- consume W_hh tile B ----
    if (b < 432) {
        mbar_wait(mb1, p1 & 1); p1++;
        float a = 0.f;
        #pragma unroll
        for (int k = 0; k < 8; k++) a += dot4(buf[1][warp * 256 + lane + 32 * k], s_vec[lane + 32 * k]);
        a = warp_sum(a);
        if (lane == 0) atomicAdd(&g_gates[4 * (592 + b) + warp], a);
        __threadfence(); __syncthreads();
        if (tid == 0) s_bcast = (atomicAdd(&g_ctr_gate, 1u) == 2047u);
        __syncthreads();
        if (s_bcast) lstm_all(c0, b_ih, b_hh, h_out, c_out, tid);
    }

    // ---- attn_applied (blocks 128..159) ----
    if (b >= L && b < L + 32) {
        if (tid == 0) spin_flag(&g_flag_sm);
        __syncthreads(); __threadfence();
        int jl = tid & 31, lg = tid >> 5;
        int j = (b - L) * 32 + jl;
        float acc = 0.f;
        #pragma unroll 8
        for (int k = 0; k < 32; k++) {
            int l = lg * 32 + k;
            acc += g_attn_scratch[l] * enc[l * H + j];
        }
        s_soft[tid] = acc; __syncthreads();
        if (lg == 0)
            g_attn_applied[j] = s_soft[jl] + s_soft[32 + jl] + s_soft[64 + jl] + s_soft[96 + jl];
        __threadfence(); __syncthreads();
        if (tid == 0) {
            if (atomicAdd(&g_ctr_aa, 1u) == 31u) { g_ctr_aa = 0u; __threadfence(); atomicExch(&g_flag_aa, 1u); }
        }
        __syncthreads();
    }

    // ---- comb (blocks 0..511, rows 2b & 2b+1) ----
    if (b < 512) {
        if (tid == 0) spin_flag(&g_flag_aa);
        __syncthreads(); __threadfence();
        mbar_wait(mb0, p0 & 1); p0++;
        int half = warp & 1, rw = warp >> 1;
        float acc = 0.f;
        #pragma unroll
        for (int k = 0; k < 8; k++) {
            int i = half * 256 + lane + 32 * k;
            float4 xv = (i < 256) ? erow4[i] : ((const float4*)g_attn_applied)[i - 256];
            acc += dot4(buf[0][rw * 512 + i], xv);
        }
        acc = warp_sum(acc);
        if (lane == 0) s_red[warp] = acc;
        __syncthreads();
        if (tid == 0) {
            g_x[2 * b]     = fmaxf(s_red[0] + s_red[1] + comb_b[2 * b],     0.f);
            g_x[2 * b + 1] = fmaxf(s_red[2] + s_red[3] + comb_b[2 * b + 1], 0.f);
            __threadfence();
            if (atomicAdd(&g_ctr_comb, 1u) == 511u) { g_ctr_comb = 0u; __threadfence(); atomicExch(&g_flag_x, 1u); }
        }
        __syncthreads();
    }

    // ---- issue W_ih tile copies (stages now free) ----
    if (tid == 0) {
        mbar_expect(mb0, TB); bulk_cp(buf[0], W_ih + (size_t)b * 4 * H, TB, mb0, pol);
        if (b < 432) { mbar_expect(mb1, TB); bulk_cp(buf[1], W_ih + (size_t)(592 + b) * 4 * H, TB, mb1, pol); }
    }

    // ---- W_ih dots (need g_x) ----
    if (tid == 0) spin_flag(&g_flag_x);
    __syncthreads(); __threadfence();
    s_vec[tid]       = ((const float4*)g_x)[tid];
    s_vec[tid + 128] = ((const float4*)g_x)[tid + 128];
    __syncthreads();

    mbar_wait(mb0, p0 & 1); p0++;
    {
        float a = 0.f;
        #pragma unroll
        for (int k = 0; k < 8; k++) a += dot4(buf[0][warp * 256 + lane + 32 * k], s_vec[lane + 32 * k]);
        a = warp_sum(a);
        if (lane == 0) atomicAdd(&g_gates[4 * b + warp], a);
    }
    __threadfence(); __syncthreads();
    if (tid == 0) s_bcast = (atomicAdd(&g_ctr_gate, 1u) == 2047u);
    __syncthreads();
    if (s_bcast) lstm_all(c0, b_ih, b_hh, h_out, c_out, tid);

    // issue first out_W tile early (overlaps gates tail + lstm)
    if (tid == 0) { mbar_expect(mb0, TB); bulk_cp(buf[0], out_W + (size_t)b * 4 * H, TB, mb0, pol); }

    if (b < 432) {
        mbar_wait(mb1, p1 & 1); p1++;
        float a = 0.f;
        #pragma unroll
        for (int k = 0; k < 8; k++) a += dot4(buf[1][warp * 256 + lane + 32 * k], s_vec[lane + 32 * k]);
        a = warp_sum(a);
        if (lane == 0) atomicAdd(&g_gates[4 * (592 + b) + warp], a);
        __threadfence(); __syncthreads();
        if (tid == 0) s_bcast = (atomicAdd(&g_ctr_gate, 1u) == 2047u);
        __syncthreads();
        if (s_bcast) lstm_all(c0, b_ih, b_hh, h_out, c_out, tid);
    }
    if (tid == 0) { mbar_expect(mb1, TB); bulk_cp(buf[1], out_W + (size_t)(b + 592) * 4 * H, TB, mb1, pol); }

    // ---- output projection (needs g_h) ----
    if (tid == 0) spin_flag(&g_flag_h);
    __syncthreads(); __threadfence();
    s_vec[tid]       = ((const float4*)g_h)[tid];
    s_vec[tid + 128] = ((const float4*)g_h)[tid + 128];
    __syncthreads();

    const int nt = 21 + (b < 132);             // 12564 = 592*21 + 132 full tiles
    float m = -INFINITY, ss = 0.f;
    for (int k = 0; k < nt; k++) {
        int s = k & 1;
        if (s == 0) { mbar_wait(mb0, p0 & 1); p0++; }
        else        { mbar_wait(mb1, p1 & 1); p1++; }
        size_t row = ((size_t)b + 592ul * k) * 4 + warp;
        float a = 0.f;
        #pragma unroll
        for (int kk = 0; kk < 8; kk++)
            a += dot4(buf[s][warp * 256 + lane + 32 * kk], s_vec[lane + 32 * kk]);
        a = warp_sum(a);
        if (lane == 0) {
            float lg = a + out_b[row];
            out[row] = lg;
            if (lg > m) { ss = ss * expf(m - lg) + 1.f; m = lg; }
            else        { ss += expf(lg - m); }
        }
        __syncthreads();
        if (tid == 0 && k + 2 < nt) {
            unsigned mb = s == 0 ? mb0 : mb1;
            mbar_expect(mb, TB);
            bulk_cp(buf[s], out_W + ((size_t)b + 592ul * (k + 2)) * 4 * H, TB, mb, pol);
        }
    }

    // tail row 50256 (block 0, warp 0)
    if (b == 0 && warp == 0) {
        const float4* w = (const float4*)(out_W + (size_t)50256 * H);
        float a = 0.f;
        #pragma unroll
        for (int kk = 0; kk < 8; kk++) a += dot4(__ldcs(w + lane + 32 * kk), s_vec[lane + 32 * kk]);
        a = warp_sum(a);
        if (lane == 0) {
            float lg = a + out_b[50256];
            out[50256] = lg;
            if (lg > m) { ss = ss * expf(m - lg) + 1.f; m = lg; }
            else        { ss += expf(lg - m); }
        }
    }

    // ---- publish per-block (max,sum); last block computes logZ ----
    if (lane == 0) { s_red[warp] = m; s_red[4 + warp] = ss; }
    __syncthreads();
    if (tid == 0) {
        float M = fmaxf(fmaxf(s_red[0], s_red[1]), fmaxf(s_red[2], s_red[3]));
        float S = 0.f;
        #pragma unroll
        for (int k = 0; k < 4; k++) S += s_red[4 + k] * expf(s_red[k] - M);
        g_bmax[b] = M; g_bsum[b] = S;
        __threadfence();
        s_bcast = (atomicAdd(&g_ctr_out, 1u) == NB - 1);
    }
    __syncthreads();
    if (s_bcast) {
        __threadfence();
        float mm = -INFINITY;
        for (int k = tid; k < NB; k += 128) mm = fmaxf(mm, g_bmax[k]);
        mm = warp_max(mm);
        if (lane == 0) s_red[warp] = mm;
        __syncthreads();
        if (tid == 0) s_red[0] = fmaxf(fmaxf(s_red[0], s_red[1]), fmaxf(s_red[2], s_red[3]));
        __syncthreads();
        float M = s_red[0];
        __syncthreads();
        float S = 0.f;
        for (int k = tid; k < NB; k += 128) S += g_bsum[k] * expf(g_bmax[k] - M);
        S = warp_sum(S);
        if (lane == 0) s_red[4 + warp] = S;
        __syncthreads();
        if (tid == 0) {
            g_logZ = M + logf(s_red[4] + s_red[5] + s_red[6] + s_red[7]);
            g_ctr_out = 0u;
            g_flag_sm = 0u; g_flag_aa = 0u; g_flag_x = 0u; g_flag_h = 0u;   // reset for replay
            __threadfence();
            atomicExch(&g_flag_z, 1u);
        }
    }

    // ---- final subtract (all blocks on own rows) ----
    if (tid == 0) spin_flag(&g_flag_z);
    __syncthreads(); __threadfence();
    float lz = g_logZ;
    for (int i = tid; i < nt * 4; i += 128) {
        size_t row = ((size_t)b + 592ul * (i >> 2)) * 4 + (i & 3);
        out[row] -= lz;
    }
    if (b == 0 && tid == 0) out[50256] -= lz;
    __threadfence(); __syncthreads();
    if (tid == 0) {
        if (atomicAdd(&g_done, 1u) == NB - 1) { g_done = 0u; __threadfence(); atomicExch(&g_flag_z, 0u); }
    }
}

extern "C" void kernel_launch(void* const* d_in, const int* in_sizes, int n_in,
                              void* d_out, int out_size) {
    const int*   tokens = (const int*)  d_in[0];
    const float* h0     = (const float*)d_in[1];
    const float* c0     = (const float*)d_in[2];
    const float* enc    = (const float*)d_in[3];
    const float* emb    = (const float*)d_in[4];
    const float* attn_W = (const float*)d_in[5];
    const float* attn_b = (const float*)d_in[6];
    const float* comb_W = (const float*)d_in[7];
    const float* comb_b = (const float*)d_in[8];
    const float* W_ih   = (const float*)d_in[9];
    const float* W_hh   = (const float*)d_in[10];
    const float* b_ih   = (const float*)d_in[11];
    const float* b_hh   = (const float*)d_in[12];
    const float* out_W  = (const float*)d_in[13];
    const float* out_b  = (const float*)d_in[14];

    float* out    = (float*)d_out;          // [V] log-probs
    float* h_out  = out + V;                // [H]
    float* c_out  = out + V + H;            // [H]
    float* aw_out = out + V + 2 * H;        // [L]

    k_fused<<<NB, 128>>>(tokens, h0, c0, enc, emb, attn_W, attn_b,
                         comb_W, comb_b, W_ih, W_hh, b_ih, b_hh,
                         out_W, out_b, out, h_out, c_out, aw_out);
}